// round 2
// baseline (speedup 1.0000x reference)
#include <cuda_runtime.h>
#include <cuda_fp16.h>

// Problem constants
#define H    2048
#define D    2048
#define L    256
#define G3   (3*H)          // 6144 gate rows
#define GRID 148            // persistent blocks (GB300 has 152 SMs; 181KB smem/block
                            // forbids double-stacking -> all 148 co-resident, barrier safe)
#define THREADS 224
#define NWARP   7
#define UMAX    14          // max hidden units per block (148*14 >= 2048)
#define NB14    124         // blocks 0..123 own 14 units, 124..147 own 13

// Scratch (device globals; no allocations allowed)
__device__ float    g_p0[D], g_p1[D], g_pc[D];
__device__ float    g_u[G3], g_v[G3], g_c[G3];
__device__ float    g_pred[L];     // per-step prediction accumulators
__device__ float    g_h[2][H];     // double-buffered hidden state
__device__ unsigned g_bar;         // grid barrier counter

// Shared memory layout (bytes)
#define W_SM_BYTES   (UMAX*3*H*2)          // 172032: fp16 W_hh slice [unit][gate][k]
#define H_SM_OFF     W_SM_BYTES            // 8192:   staged h (fp32)
#define C_SM_OFF     (H_SM_OFF + H*4)      // per-unit constants
#define SMEM_BYTES   (C_SM_OFF + 4*(3*3*UMAX + 2*UMAX + NWARP + 2) + 64)

// ---------------------------------------------------------------------------
// prep_small: fold the 7-dim input path into three D-vectors; reset state.
// x7 = [pk, tp, dose, emb0, emb1, emb2, route]
// ---------------------------------------------------------------------------
__global__ void prep_small(const float* __restrict__ W_pre, const float* __restrict__ b_pre,
                           const float* __restrict__ dose,  const float* __restrict__ route,
                           const int*   __restrict__ pat_,  const float* __restrict__ emb_table,
                           const float* __restrict__ pk_data, float* __restrict__ out)
{
    int tid = threadIdx.x;
    int pat = pat_[0];
    float ds = dose[0], rt = route[0];
    float e0 = emb_table[pat*3+0], e1 = emb_table[pat*3+1], e2 = emb_table[pat*3+2];
    for (int d = tid; d < D; d += blockDim.x) {
        const float* w = W_pre + d*7;
        g_p0[d] = w[0];
        g_p1[d] = w[1];
        g_pc[d] = ds*w[2] + e0*w[3] + e1*w[4] + e2*w[5] + rt*w[6] + b_pre[d];
    }
    for (int i = tid; i < L; i += blockDim.x) g_pred[i] = 0.f;
    if (tid == 0) { g_bar = 0u; out[0] = pk_data[0]; }
}

// ---------------------------------------------------------------------------
// prep_uvc: u = W_ih@p0, v = W_ih@p1, c = W_ih@pc + b_ih (+ b_hh for r,z rows).
// One warp per gate row. Reads W_ih (50MB) once from HBM.
// ---------------------------------------------------------------------------
__global__ void prep_uvc(const float* __restrict__ W_ih, const float* __restrict__ b_ih,
                         const float* __restrict__ b_hh)
{
    int w = threadIdx.x >> 5, lane = threadIdx.x & 31;
    int g = blockIdx.x * 8 + w;
    const float4* wr  = (const float4*)(W_ih + (size_t)g * D);
    const float4* p04 = (const float4*)g_p0;
    const float4* p14 = (const float4*)g_p1;
    const float4* pc4 = (const float4*)g_pc;
    float au = 0.f, av = 0.f, ac = 0.f;
    for (int i = lane; i < D/4; i += 32) {
        float4 wv = wr[i], a = p04[i], bb = p14[i], c = pc4[i];
        au += wv.x*a.x  + wv.y*a.y  + wv.z*a.z  + wv.w*a.w;
        av += wv.x*bb.x + wv.y*bb.y + wv.z*bb.z + wv.w*bb.w;
        ac += wv.x*c.x  + wv.y*c.y  + wv.z*c.z  + wv.w*c.w;
    }
    #pragma unroll
    for (int o = 16; o; o >>= 1) {
        au += __shfl_down_sync(0xffffffffu, au, o);
        av += __shfl_down_sync(0xffffffffu, av, o);
        ac += __shfl_down_sync(0xffffffffu, ac, o);
    }
    if (lane == 0) {
        g_u[g] = au; g_v[g] = av;
        float cc = ac + b_ih[g];
        if (g < 2*H) cc += b_hh[g];     // b_hh folds into r,z pre-activations only
        g_c[g] = cc;
    }
}

// ---------------------------------------------------------------------------
// Persistent GRU scan. One block per 13-14 hidden units; W_hh slice lives in
// smem as fp16 for all 255 steps. Grid barrier via global atomic counter.
// ---------------------------------------------------------------------------
__global__ void __launch_bounds__(THREADS, 1)
gru_kernel(const float* __restrict__ W_hh, const float* __restrict__ b_hh,
           const float* __restrict__ W_out, const float* __restrict__ b_out,
           const float* __restrict__ smiles, const float* __restrict__ pk_data,
           const float* __restrict__ timepoints, const int* __restrict__ tf_mask,
           float* __restrict__ out)
{
    extern __shared__ char smem_raw[];
    half*  w_sm  = (half*)smem_raw;                  // [42][2048] fp16
    float* h_sm  = (float*)(smem_raw + H_SM_OFF);    // [2048]
    float* cbase = (float*)(smem_raw + C_SM_OFF);
    float* cu    = cbase;                 // [42] pk coefficient
    float* cv    = cu + 3*UMAX;           // [42] tp coefficient
    float* cc    = cv + 3*UMAX;           // [42] constant (incl biases)
    float* bhn   = cc + 3*UMAX;           // [14] b_hh n-row (multiplied by r)
    float* wo    = bhn + UMAX;            // [14] W_out slice
    float* ppart = wo + UMAX;             // [7]  per-warp pred partials
    float* s_sc  = ppart + NWARP;         // [2]  pk, tp broadcast

    const int tid  = threadIdx.x;
    const int lane = tid & 31;
    const int w    = tid >> 5;
    const int b    = blockIdx.x;
    const int ustart = (b < NB14) ? 14*b : 14*NB14 + 13*(b - NB14);
    const int upb    = (b < NB14) ? 14 : 13;

    // ---- prologue: load W_hh slice fp32->fp16 into smem ----
    const int nrow = 3*upb;
    for (int i = tid; i < nrow*(H/4); i += THREADS) {
        int lr = i >> 9;                 // local row (unit*3 + gate)
        int k4 = i & 511;
        int lu = lr / 3, gate = lr - 3*lu;
        int grow = gate*H + ustart + lu;
        float4 v = *(const float4*)(W_hh + (size_t)grow*H + k4*4);
        *(half2*)(w_sm + lr*H + k4*4)     = __floats2half2_rn(v.x, v.y);
        *(half2*)(w_sm + lr*H + k4*4 + 2) = __floats2half2_rn(v.z, v.w);
    }
    if (upb == 13) {  // zero rows 39..41 so guard-free hot loop is harmless
        for (int i = tid; i < 3*H; i += THREADS) w_sm[39*H + i] = __float2half(0.f);
    }
    for (int j = tid; j < upb*3; j += THREADS) {
        int lu = j/3, gate = j - 3*lu;
        int grow = gate*H + ustart + lu;
        cu[j] = g_u[grow]; cv[j] = g_v[grow]; cc[j] = g_c[grow];
    }
    for (int j = tid; j < upb; j += THREADS) {
        bhn[j] = b_hh[2*H + ustart + j];
        wo[j]  = W_out[ustart + j];
    }
    const float bo = b_out[0];
    if (tid == 0) { s_sc[0] = pk_data[0]; s_sc[1] = timepoints[0]; }

    const int u0 = 2*w;                         // local units u0, u0+1
    int nu = upb - u0; nu = nu < 0 ? 0 : (nu > 2 ? 2 : nu);
    const half* wb = w_sm + (u0*3)*H;

    for (int t = 0; t < L-1; ++t) {
        // stage h_t into smem; MUST bypass L1 (persists across steps within launch)
        const float4* hsrc = (const float4*)((t == 0) ? smiles : g_h[(t-1)&1]);
        float4* hd = (float4*)h_sm;
        for (int i = tid; i < H/4; i += THREADS) hd[i] = __ldcg(hsrc + i);

        // prefetch next-step scalars (read-only inputs, any cache fine)
        int tfn = 0; float pkteach = 0.f, tpn = 0.f;
        if (tid == 0) {
            tfn = __ldg(&tf_mask[t+1]); pkteach = __ldg(&pk_data[t+1]); tpn = __ldg(&timepoints[t+1]);
        }
        __syncthreads();
        const float pk = s_sc[0], tp = s_sc[1];

        // 6 dot products (2 units x 3 gates) over k=0..2047, fp16 weights, fp32 acc
        float acc[6] = {0.f,0.f,0.f,0.f,0.f,0.f};
        #pragma unroll
        for (int ck = 0; ck < 8; ++ck) {
            const int k0 = ck*256 + lane*8;
            const float4 ha = *(const float4*)(h_sm + k0);
            const float4 hb = *(const float4*)(h_sm + k0 + 4);
            #pragma unroll
            for (int r = 0; r < 6; ++r) {
                const uint4 wv = *(const uint4*)(wb + r*H + k0);
                float2 f0 = __half22float2(*(const half2*)&wv.x);
                float2 f1 = __half22float2(*(const half2*)&wv.y);
                float2 f2 = __half22float2(*(const half2*)&wv.z);
                float2 f3 = __half22float2(*(const half2*)&wv.w);
                acc[r] = fmaf(f0.x, ha.x, acc[r]); acc[r] = fmaf(f0.y, ha.y, acc[r]);
                acc[r] = fmaf(f1.x, ha.z, acc[r]); acc[r] = fmaf(f1.y, ha.w, acc[r]);
                acc[r] = fmaf(f2.x, hb.x, acc[r]); acc[r] = fmaf(f2.y, hb.y, acc[r]);
                acc[r] = fmaf(f3.x, hb.z, acc[r]); acc[r] = fmaf(f3.y, hb.w, acc[r]);
            }
        }
        #pragma unroll
        for (int o = 16; o; o >>= 1) {
            #pragma unroll
            for (int r = 0; r < 6; ++r)
                acc[r] += __shfl_down_sync(0xffffffffu, acc[r], o);
        }

        // gate math + h update (lane 0 of each warp, its 1-2 units)
        if (lane == 0) {
            float pp = 0.f;
            #pragma unroll
            for (int un = 0; un < 2; ++un) {
                if (un < nu) {
                    const int j = u0 + un, cb = j*3;
                    const float dr = acc[un*3], dz = acc[un*3+1], dn = acc[un*3+2];
                    const float ar = fmaf(pk, cu[cb],   fmaf(tp, cv[cb],   cc[cb]))   + dr;
                    const float az = fmaf(pk, cu[cb+1], fmaf(tp, cv[cb+1], cc[cb+1])) + dz;
                    const float r  = 1.f/(1.f + __expf(-ar));
                    const float z  = 1.f/(1.f + __expf(-az));
                    const float an = fmaf(pk, cu[cb+2], fmaf(tp, cv[cb+2], cc[cb+2]))
                                   + r*(dn + bhn[j]);
                    const float n  = tanhf(an);
                    const float hnew = fmaf(1.f - z, n, z * h_sm[ustart + j]);
                    g_h[t&1][ustart + j] = hnew;
                    pp += wo[j]*hnew;
                }
            }
            ppart[w] = pp;
        }
        __syncthreads();

        // grid barrier + pred reduction + pk feedback (thread 0 only)
        if (tid == 0) {
            float s = 0.f;
            #pragma unroll
            for (int i = 0; i < NWARP; ++i) s += ppart[i];
            atomicAdd(&g_pred[t], s);
            __threadfence();                          // release h writes + pred add
            atomicAdd(&g_bar, 1u);
            const unsigned target = (unsigned)GRID * (unsigned)(t+1);
            volatile unsigned* vb = &g_bar;
            while (*vb < target) { }
            __threadfence();                          // acquire other blocks' writes
            const float pred = *((volatile float*)&g_pred[t]) + bo;
            if (b == 0) out[t+1] = pred;
            s_sc[0] = (tfn == 1) ? pred : pkteach;    // teacher forcing select
            s_sc[1] = tpn;
        }
        __syncthreads();
    }
}

// ---------------------------------------------------------------------------
// Input order (metadata): 0 timepoints, 1 pk_data, 2 input_len, 3 emb_patient,
// 4 drug_route, 5 dose, 6 smiles, 7 tf_mask, 8 emb_table, 9 W_pre, 10 b_pre,
// 11 W_ih, 12 W_hh, 13 b_ih, 14 b_hh, 15 W_out, 16 b_out
// ---------------------------------------------------------------------------
extern "C" void kernel_launch(void* const* d_in, const int* in_sizes, int n_in,
                              void* d_out, int out_size)
{
    const float* timepoints = (const float*)d_in[0];
    const float* pk_data    = (const float*)d_in[1];
    const int*   pat        = (const int*)  d_in[3];
    const float* route      = (const float*)d_in[4];
    const float* dose       = (const float*)d_in[5];
    const float* smiles     = (const float*)d_in[6];
    const int*   tf_mask    = (const int*)  d_in[7];
    const float* emb_table  = (const float*)d_in[8];
    const float* W_pre      = (const float*)d_in[9];
    const float* b_pre      = (const float*)d_in[10];
    const float* W_ih       = (const float*)d_in[11];
    const float* W_hh       = (const float*)d_in[12];
    const float* b_ih       = (const float*)d_in[13];
    const float* b_hh       = (const float*)d_in[14];
    const float* W_out      = (const float*)d_in[15];
    const float* b_out      = (const float*)d_in[16];
    float* out = (float*)d_out;

    cudaFuncSetAttribute(gru_kernel, cudaFuncAttributeMaxDynamicSharedMemorySize, SMEM_BYTES);

    prep_small<<<1, 256>>>(W_pre, b_pre, dose, route, pat, emb_table, pk_data, out);
    prep_uvc<<<G3/8, 256>>>(W_ih, b_ih, b_hh);
    gru_kernel<<<GRID, THREADS, SMEM_BYTES>>>(W_hh, b_hh, W_out, b_out, smiles,
                                              pk_data, timepoints, tf_mask, out);
}